// round 2
// baseline (speedup 1.0000x reference)
#include <cuda_runtime.h>

#define TB   64      // batch
#define TT   512     // timesteps
#define DIN  64
#define DM   512     // d_model
#define DOUT 64
#define NCB  16      // column blocks
#define NC   32      // cols per CTA
#define NBB  8       // batch blocks
#define NB   8       // batches per CTA
#define GB   128     // persistent grid

// ---- device scratch (allocation-free) --------------------------------------
__device__ float g_pre0 [TT * TB * DM];   // [t][b][j]  x@Wih0 + biases
__device__ float g_h1all[TT * TB * DM];   // [t][b][j]  layer-1 hidden history
__device__ float g_h0   [2 * TB * DM];    // ping-pong h0
__device__ float g_h1   [2 * TB * DM];    // ping-pong h1
__device__ unsigned int g_bars[NBB];      // per-batchblock barrier counters

// ---------------------------------------------------------------------------
// k_pre: pre0[t][b][:] = x[b][t][:] @ Wih0 + (bih0 + bhh0)
// grid 512 (one block per t), 256 thr, dyn smem 149504 B.
// Block 0 resets barrier counters; blocks t<128 zero parity-1 hidden state.
// ---------------------------------------------------------------------------
__global__ void __launch_bounds__(256, 1)
k_pre(const float* __restrict__ data, const float* __restrict__ Wih0,
      const float* __restrict__ bih0, const float* __restrict__ bhh0)
{
    extern __shared__ float sm[];
    float* xs = sm;                 // [64][64]
    float* Ws = sm + TB * DIN;      // [64][512]
    float* bs = Ws + DIN * DM;      // [512]

    const int t = blockIdx.x, tid = threadIdx.x;
    if (t == 0 && tid < NBB) g_bars[tid] = 0u;
    if (t < 128) {                                  // zero parity-1 h (t=0 reads it)
        int i = t * 256 + tid;                      // 0..32767
        g_h0[TB * DM + i] = 0.0f;
        g_h1[TB * DM + i] = 0.0f;
    }

    for (int i = tid; i < TB * DIN; i += 256) {
        int b = i >> 6, k = i & 63;
        xs[b * DIN + k] = data[(b * TT + t) * DIN + k];
    }
    for (int i = tid; i < DIN * DM; i += 256) Ws[i] = Wih0[i];
    for (int i = tid; i < DM; i += 256)       bs[i] = bih0[i] + bhh0[i];
    __syncthreads();

    // 64 batches x 128 float4-cols = 8192 units; 32 per thread
    for (int it = 0; it < 32; it++) {
        int u  = tid + 256 * it;
        int b  = u >> 7;            // same across warp -> broadcast xs reads
        int j4 = u & 127;
        float4 acc = *(const float4*)&bs[j4 * 4];
        const float* xr = &xs[b * DIN];
        #pragma unroll 8
        for (int k = 0; k < DIN; k++) {
            float  x = xr[k];
            float4 w = *(const float4*)&Ws[k * DM + j4 * 4];
            acc.x = fmaf(x, w.x, acc.x);
            acc.y = fmaf(x, w.y, acc.y);
            acc.z = fmaf(x, w.z, acc.z);
            acc.w = fmaf(x, w.w, acc.w);
        }
        *(float4*)&g_pre0[(t * TB + b) * DM + j4 * 4] = acc;
    }
}

// ---------------------------------------------------------------------------
// per-batchblock grid barrier: 16 CTAs (the col-blocks of one batch-block).
// All 128 CTAs are co-resident (1 CTA/SM by smem, grid <= 148 SMs).
// ---------------------------------------------------------------------------
__device__ __forceinline__ void gsync(int bb, unsigned int* tgt)
{
    *tgt += NCB;
    __threadfence();              // release each thread's global writes
    __syncthreads();
    if (threadIdx.x == 0) {
        atomicAdd(&g_bars[bb], 1u);
        while (*(volatile unsigned int*)&g_bars[bb] < *tgt) { }
    }
    __syncthreads();              // orders spin before other threads' reads
}

// copy 4096 floats (8 batch rows of h) global -> smem, L2-coherent
__device__ __forceinline__ void stage(float* dst, const float* src, int tid)
{
    const float4* s = (const float4*)src;
    float4*       d = (float4*)dst;
    #pragma unroll
    for (int j = 0; j < 4; j++) d[tid + 256 * j] = __ldcg(&s[tid + 256 * j]);
}

// ---------------------------------------------------------------------------
// k_seq: 512 sequential steps. 128 CTAs x 256 thr, dyn smem 229504 B.
// CTA (bb,cb) owns batches [8bb,8bb+8) x cols [32cb,32cb+32).
// Weights SMEM-resident, interleaved float4 over k: W[kg][c] = (W[4kg..4kg+3][c]).
// Split-k: warp w covers k in [64w, 64w+64) for ALL 8 batches -> each weight
// byte read once per CTA per step. Partials reduced through smem.
// ---------------------------------------------------------------------------
__global__ void __launch_bounds__(256, 1)
k_seq(const float* __restrict__ Whh0, const float* __restrict__ Wih1,
      const float* __restrict__ bih1, const float* __restrict__ Whh1,
      const float* __restrict__ bhh1)
{
    extern __shared__ float sm[];
    float4* W0  = (float4*)sm;          // [4096] float4 (Whh0 slice)
    float4* W1  = W0 + 4096;            // Wih1 slice
    float4* W2  = W1 + 4096;            // Whh1 slice
    float*  h0s = sm + 3 * 16384;       // [8][512]
    float*  h1s = h0s + NB * DM;        // [8][512] (aliases phase-1 red buffer)
    float*  b1s = h1s + NB * DM;        // [32]

    const int tid = threadIdx.x;
    const int cb  = blockIdx.x & (NCB - 1);
    const int bb  = blockIdx.x >> 4;
    const int c0  = cb * NC, b0 = bb * NB;

    // stage weight slices (interleaved float4 along k)
    for (int idx = tid; idx < 4096; idx += 256) {
        int kg = idx >> 5, c = idx & 31;
        int kb = kg * 4, cg = c0 + c;
        float4 v;
        v.x = Whh0[(kb+0)*DM+cg]; v.y = Whh0[(kb+1)*DM+cg];
        v.z = Whh0[(kb+2)*DM+cg]; v.w = Whh0[(kb+3)*DM+cg];
        W0[idx] = v;
        v.x = Wih1[(kb+0)*DM+cg]; v.y = Wih1[(kb+1)*DM+cg];
        v.z = Wih1[(kb+2)*DM+cg]; v.w = Wih1[(kb+3)*DM+cg];
        W1[idx] = v;
        v.x = Whh1[(kb+0)*DM+cg]; v.y = Whh1[(kb+1)*DM+cg];
        v.z = Whh1[(kb+2)*DM+cg]; v.w = Whh1[(kb+3)*DM+cg];
        W2[idx] = v;
    }
    if (tid < NC) b1s[tid] = bih1[c0 + tid] + bhh1[c0 + tid];
    __syncthreads();

    const int w   = tid >> 5;     // warp id = k-slice id = batch id in reduction
    const int lc  = tid & 31;     // lane = local col
    const int kg0 = w * 16;       // warp's float4-k range [kg0, kg0+16)
    unsigned int tgt = 0;
    float acc[8];

    for (int t = 0; t < TT; t++) {
        const int p = t & 1, rp = p ^ 1;

        // ===== phase 1: h0_new = tanh(pre0[t] + h0_prev @ Whh0) =====
        stage(h0s, g_h0 + rp * TB * DM + b0 * DM, tid);
        __syncthreads();

        #pragma unroll
        for (int b = 0; b < 8; b++) acc[b] = 0.0f;
        #pragma unroll 4
        for (int kg = kg0; kg < kg0 + 16; kg++) {
            float4 wv = W0[kg * 32 + lc];
            #pragma unroll
            for (int b = 0; b < 8; b++) {
                float4 h = *(const float4*)&h0s[b * DM + kg * 4]; // broadcast
                acc[b] = fmaf(h.x, wv.x, acc[b]);
                acc[b] = fmaf(h.y, wv.y, acc[b]);
                acc[b] = fmaf(h.z, wv.z, acc[b]);
                acc[b] = fmaf(h.w, wv.w, acc[b]);
            }
        }
        float* red = h1s;   // h1s free until phase-2 staging
        #pragma unroll
        for (int b = 0; b < 8; b++) red[(w * 8 + b) * 32 + lc] = acc[b];
        __syncthreads();
        {
            float s = g_pre0[(t * TB + b0 + w) * DM + c0 + lc];
            #pragma unroll
            for (int r = 0; r < 8; r++) s += red[(r * 8 + w) * 32 + lc];
            g_h0[p * TB * DM + (b0 + w) * DM + c0 + lc] = tanhf(s);
        }
        gsync(bb, &tgt);    // barrier A: h0_new visible across col-blocks

        // ===== phase 2: h1_new = tanh(b1 + h0_new@Wih1 + h1_prev@Whh1) =====
        stage(h0s, g_h0 + p  * TB * DM + b0 * DM, tid);
        stage(h1s, g_h1 + rp * TB * DM + b0 * DM, tid);
        __syncthreads();

        #pragma unroll
        for (int b = 0; b < 8; b++) acc[b] = 0.0f;
        #pragma unroll 2
        for (int kg = kg0; kg < kg0 + 16; kg++) {
            float4 u1 = W1[kg * 32 + lc];
            float4 u2 = W2[kg * 32 + lc];
            #pragma unroll
            for (int b = 0; b < 8; b++) {
                float4 a  = *(const float4*)&h0s[b * DM + kg * 4];
                float4 c4 = *(const float4*)&h1s[b * DM + kg * 4];
                acc[b] = fmaf(a.x,  u1.x, acc[b]);
                acc[b] = fmaf(a.y,  u1.y, acc[b]);
                acc[b] = fmaf(a.z,  u1.z, acc[b]);
                acc[b] = fmaf(a.w,  u1.w, acc[b]);
                acc[b] = fmaf(c4.x, u2.x, acc[b]);
                acc[b] = fmaf(c4.y, u2.y, acc[b]);
                acc[b] = fmaf(c4.z, u2.z, acc[b]);
                acc[b] = fmaf(c4.w, u2.w, acc[b]);
            }
        }
        float* red2 = h0s;
        __syncthreads();    // all warps done reading h0s before overwrite
        #pragma unroll
        for (int b = 0; b < 8; b++) red2[(w * 8 + b) * 32 + lc] = acc[b];
        __syncthreads();
        {
            float s = b1s[lc];
            #pragma unroll
            for (int r = 0; r < 8; r++) s += red2[(r * 8 + w) * 32 + lc];
            float hn = tanhf(s);
            int gi = (b0 + w) * DM + c0 + lc;
            g_h1[p * TB * DM + gi]   = hn;
            g_h1all[t * TB * DM + gi] = hn;
        }
        gsync(bb, &tgt);    // barrier B: h1_new visible, WAR-safe for next step
    }
}

// ---------------------------------------------------------------------------
// k_out: out[b][t][:] = h1all[t][b][:] @ Wout + bout
// grid 512 (per t), 256 thr, dyn smem 163840 B. k-chunked h staging.
// ---------------------------------------------------------------------------
__global__ void __launch_bounds__(256, 1)
k_out(const float* __restrict__ Wout, const float* __restrict__ bout,
      float* __restrict__ out)
{
    extern __shared__ float sm[];
    float* Ws = sm;                 // [512][64]
    float* hs = Ws + DM * DOUT;     // [64][128] k-chunk

    const int t = blockIdx.x, tid = threadIdx.x;
    for (int i = tid; i < DM * DOUT; i += 256) Ws[i] = Wout[i];

    const int j  = tid & 63;        // output col
    const int bq = tid >> 6;        // batch quarter
    float acc[16];
    #pragma unroll
    for (int i = 0; i < 16; i++) acc[i] = 0.0f;

    for (int kc = 0; kc < 4; kc++) {
        __syncthreads();
        for (int idx = tid; idx < TB * 128; idx += 256) {
            int b = idx >> 7, kk = idx & 127;
            hs[idx] = g_h1all[(t * TB + b) * DM + kc * 128 + kk];
        }
        __syncthreads();
        for (int kk = 0; kk < 128; kk++) {
            float wv = Ws[(kc * 128 + kk) * DOUT + j];
            #pragma unroll
            for (int i = 0; i < 16; i++)
                acc[i] = fmaf(hs[(bq * 16 + i) * 128 + kk], wv, acc[i]);
        }
    }
    float bj = bout[j];
    #pragma unroll
    for (int i = 0; i < 16; i++) {
        int b = bq * 16 + i;
        out[(b * TT + t) * DOUT + j] = acc[i] + bj;
    }
}

// ---------------------------------------------------------------------------
extern "C" void kernel_launch(void* const* d_in, const int* in_sizes, int n_in,
                              void* d_out, int out_size)
{
    const float* data = (const float*)d_in[0];
    const float* Wih0 = (const float*)d_in[1];
    const float* bih0 = (const float*)d_in[2];
    const float* Whh0 = (const float*)d_in[3];
    const float* bhh0 = (const float*)d_in[4];
    const float* Wih1 = (const float*)d_in[5];
    const float* bih1 = (const float*)d_in[6];
    const float* Whh1 = (const float*)d_in[7];
    const float* bhh1 = (const float*)d_in[8];
    const float* Wout = (const float*)d_in[9];
    const float* bout = (const float*)d_in[10];
    float* out = (float*)d_out;

    cudaFuncSetAttribute(k_pre, cudaFuncAttributeMaxDynamicSharedMemorySize, 149504);
    cudaFuncSetAttribute(k_seq, cudaFuncAttributeMaxDynamicSharedMemorySize, 229504);
    cudaFuncSetAttribute(k_out, cudaFuncAttributeMaxDynamicSharedMemorySize, 163840);

    k_pre<<<TT, 256, 149504>>>(data, Wih0, bih0, bhh0);
    k_seq<<<GB, 256, 229504>>>(Whh0, Wih1, bih1, Whh1, bhh1);
    k_out<<<TT, 256, 163840>>>(Wout, bout, out);
}